// round 1
// baseline (speedup 1.0000x reference)
#include <cuda_runtime.h>
#include <math.h>

#define NN 100000
#define EE 1000000
#define F  64
#define F2 32          // float2 elements per row
#define C1 4
#define C2 3
#define NPB 8          // nodes per block (8 warps)
#define ALPHA 0.1f

// ---------------- scratch (device globals, no allocation) ----------------
__device__ int   g_cnt[NN];
__device__ float g_dinv[NN];
__device__ int   g_rowptr[NN + 1];
__device__ int   g_cursor[NN];
__device__ int   g_src[EE];
__device__ float g_w[EE];
__device__ float g_xa[NN * F];
__device__ float g_xb[NN * F];

// ---------------- CSR build ----------------
__global__ void k_zero_cnt() {
    int i = blockIdx.x * blockDim.x + threadIdx.x;
    if (i < NN) g_cnt[i] = 0;
}

__global__ void k_hist(const int* __restrict__ col) {
    int e = blockIdx.x * blockDim.x + threadIdx.x;
    if (e < EE) atomicAdd(&g_cnt[col[e]], 1);
}

// single-block exclusive scan over N=100000 counts; also writes dinv, cursor
__global__ void k_scan() {
    __shared__ int sums[1024];
    int t = threadIdx.x;
    const int CH = (NN + 1023) / 1024;   // 98
    int beg = t * CH;
    int end = beg + CH; if (end > NN) end = NN;
    int s = 0;
    for (int i = beg; i < end; i++) s += g_cnt[i];
    sums[t] = s;
    __syncthreads();
    for (int off = 1; off < 1024; off <<= 1) {
        int v = (t >= off) ? sums[t - off] : 0;
        __syncthreads();
        sums[t] += v;
        __syncthreads();
    }
    int run = (t > 0) ? sums[t - 1] : 0;
    for (int i = beg; i < end; i++) {
        g_rowptr[i] = run;
        g_cursor[i] = run;
        g_dinv[i]   = rsqrtf((float)g_cnt[i] + 1.0f);  // +1 self-loop
        run += g_cnt[i];
    }
    if (t == 1023) g_rowptr[NN] = run;   // == EE
}

__global__ void k_scatter(const int* __restrict__ ei) {
    int e = blockIdx.x * blockDim.x + threadIdx.x;
    if (e < EE) {
        int s = ei[e];          // row (source)
        int d = ei[EE + e];     // col (target)
        int p = atomicAdd(&g_cursor[d], 1);
        g_src[p] = s;
        g_w[p]   = g_dinv[s] * g_dinv[d];
    }
}

// ---------------- fused GCN2Conv layer: prop + residual + GEMM + relu ----
__global__ void __launch_bounds__(256)
k_layer(const float* __restrict__ x_in, float* __restrict__ x_out,
        const float* __restrict__ W) {
    __shared__ float Wsh[F * F];
    __shared__ float hs[NPB][F];
    int t = threadIdx.x;
#pragma unroll
    for (int i = 0; i < 16; i++) Wsh[t + i * 256] = W[t + i * 256];
    __syncthreads();

    int warp = t >> 5, lane = t & 31;
    int n = blockIdx.x * NPB + warp;
    if (n < NN) {
        const float2* x2 = (const float2*)x_in;
        float2 acc = make_float2(0.f, 0.f);
        int e = g_rowptr[n], end = g_rowptr[n + 1];
        for (; e < end; e++) {
            int   s  = __ldg(&g_src[e]);
            float wv = __ldg(&g_w[e]);
            float2 v = x2[(size_t)s * F2 + lane];
            acc.x = fmaf(wv, v.x, acc.x);
            acc.y = fmaf(wv, v.y, acc.y);
        }
        float  dn = g_dinv[n];
        float2 xn = x2[(size_t)n * F2 + lane];
        float  sn = dn * dn;                  // self-loop weight
        float hx = (1.f - ALPHA) * (acc.x + sn * xn.x) + ALPHA * xn.x;
        float hy = (1.f - ALPHA) * (acc.y + sn * xn.y) + ALPHA * xn.y;
        hs[warp][2 * lane]     = hx;
        hs[warp][2 * lane + 1] = hy;
        __syncwarp();
        float o0 = 0.f, o1 = 0.f;
#pragma unroll
        for (int k = 0; k < F; k++) {
            float hv = hs[warp][k];
            float2 wk = *(const float2*)&Wsh[k * F + 2 * lane];
            o0 = fmaf(hv, wk.x, o0);
            o1 = fmaf(hv, wk.y, o1);
        }
        float2 r;
        r.x = fmaxf(o0, 0.f);
        r.y = fmaxf(o1, 0.f);
        ((float2*)x_out)[(size_t)n * F2 + lane] = r;
    }
}

// ---------------- y = x @ W_gcn (no relu, no bias) ----------------
__global__ void __launch_bounds__(256)
k_gemm(const float* __restrict__ x_in, float* __restrict__ x_out,
       const float* __restrict__ W) {
    __shared__ float Wsh[F * F];
    __shared__ float hs[NPB][F];
    int t = threadIdx.x;
#pragma unroll
    for (int i = 0; i < 16; i++) Wsh[t + i * 256] = W[t + i * 256];
    __syncthreads();

    int warp = t >> 5, lane = t & 31;
    int n = blockIdx.x * NPB + warp;
    if (n < NN) {
        const float2* x2 = (const float2*)x_in;
        float2 xn = x2[(size_t)n * F2 + lane];
        hs[warp][2 * lane]     = xn.x;
        hs[warp][2 * lane + 1] = xn.y;
        __syncwarp();
        float o0 = 0.f, o1 = 0.f;
#pragma unroll
        for (int k = 0; k < F; k++) {
            float hv = hs[warp][k];
            float2 wk = *(const float2*)&Wsh[k * F + 2 * lane];
            o0 = fmaf(hv, wk.x, o0);
            o1 = fmaf(hv, wk.y, o1);
        }
        ((float2*)x_out)[(size_t)n * F2 + lane] = make_float2(o0, o1);
    }
}

// ---------------- final: h = prop(y)+b_gcn ; out1 = h@W1+b1 ; out2 = h@W2+b2
__global__ void __launch_bounds__(256)
k_final(const float* __restrict__ y, float* __restrict__ out,
        const float* __restrict__ W1, const float* __restrict__ b1,
        const float* __restrict__ W2, const float* __restrict__ b2,
        const float* __restrict__ bg) {
    __shared__ float W1s[F * C1];
    __shared__ float W2s[F * C2];
    __shared__ float bgs[F];
    int t = threadIdx.x;
    if (t < F * C1) W1s[t] = W1[t];
    if (t < F * C2) W2s[t] = W2[t];
    if (t < F)      bgs[t] = bg[t];
    __syncthreads();

    int warp = t >> 5, lane = t & 31;
    int n = blockIdx.x * NPB + warp;
    if (n < NN) {
        const float2* y2 = (const float2*)y;
        float2 acc = make_float2(0.f, 0.f);
        int e = g_rowptr[n], end = g_rowptr[n + 1];
        for (; e < end; e++) {
            int   s  = __ldg(&g_src[e]);
            float wv = __ldg(&g_w[e]);
            float2 v = y2[(size_t)s * F2 + lane];
            acc.x = fmaf(wv, v.x, acc.x);
            acc.y = fmaf(wv, v.y, acc.y);
        }
        float  dn = g_dinv[n];
        float2 yn = y2[(size_t)n * F2 + lane];
        float  sn = dn * dn;
        float hx = acc.x + sn * yn.x + bgs[2 * lane];
        float hy = acc.y + sn * yn.y + bgs[2 * lane + 1];

        // write h (third output)
        float* out_h = out + (size_t)NN * (C1 + C2);
        ((float2*)out_h)[(size_t)n * F2 + lane] = make_float2(hx, hy);

        // heads: warp-wide dot products
        float p[C1 + C2];
#pragma unroll
        for (int c = 0; c < C1; c++)
            p[c] = hx * W1s[(2 * lane) * C1 + c] + hy * W1s[(2 * lane + 1) * C1 + c];
#pragma unroll
        for (int c = 0; c < C2; c++)
            p[C1 + c] = hx * W2s[(2 * lane) * C2 + c] + hy * W2s[(2 * lane + 1) * C2 + c];
#pragma unroll
        for (int off = 16; off; off >>= 1) {
#pragma unroll
            for (int c = 0; c < C1 + C2; c++)
                p[c] += __shfl_down_sync(0xffffffffu, p[c], off);
        }
        if (lane == 0) {
#pragma unroll
            for (int c = 0; c < C1; c++)
                out[(size_t)n * C1 + c] = p[c] + __ldg(&b1[c]);
            float* o2 = out + (size_t)NN * C1;
#pragma unroll
            for (int c = 0; c < C2; c++)
                o2[(size_t)n * C2 + c] = p[C1 + c] + __ldg(&b2[c]);
        }
    }
}

// ---------------- launch ----------------
extern "C" void kernel_launch(void* const* d_in, const int* in_sizes, int n_in,
                              void* d_out, int out_size) {
    const float* x   = (const float*)d_in[0];
    const int*   ei  = (const int*)  d_in[1];
    const float* Ws  = (const float*)d_in[2];
    const float* Wg  = (const float*)d_in[3];
    const float* bg  = (const float*)d_in[4];
    const float* W1  = (const float*)d_in[5];
    const float* b1  = (const float*)d_in[6];
    const float* W2  = (const float*)d_in[7];
    const float* b2  = (const float*)d_in[8];
    float* out = (float*)d_out;

    float *xa, *xb;
    cudaGetSymbolAddress((void**)&xa, g_xa);
    cudaGetSymbolAddress((void**)&xb, g_xb);

    k_zero_cnt<<<(NN + 255) / 256, 256>>>();
    k_hist<<<(EE + 255) / 256, 256>>>(ei + EE);
    k_scan<<<1, 1024>>>();
    k_scatter<<<(EE + 255) / 256, 256>>>(ei);

    int gb = (NN + NPB - 1) / NPB;
    k_layer<<<gb, 256>>>(x,  xa, Ws);              // layer 0
    k_layer<<<gb, 256>>>(xa, xb, Ws + F * F);      // layer 1
    k_layer<<<gb, 256>>>(xb, xa, Ws + 2 * F * F);  // layer 2
    k_gemm <<<gb, 256>>>(xa, xb, Wg);              // y = x @ W_gcn
    k_final<<<gb, 256>>>(xb, out, W1, b1, W2, b2, bg);
}

// round 5
// speedup vs baseline: 1.1012x; 1.1012x over previous
#include <cuda_runtime.h>
#include <math.h>

#define NN 100000
#define EE 1000000
#define F  64
#define F4 16          // float4 elements per row
#define C1 4
#define C2 3
#define ALPHA 0.1f
#define HPAD 68        // padded hs row (floats)

struct alignas(8) Edge { int s; float w; };

// ---------------- scratch (device globals, no allocation) ----------------
__device__ int   g_cnt[NN];
__device__ float g_dinv[NN];
__device__ int   g_rowptr[NN + 1];
__device__ int   g_cursor[NN];
__device__ Edge  g_edge[EE];
__device__ float g_xa[NN * F];
__device__ float g_xb[NN * F];

// ---------------- CSR build ----------------
__global__ void k_zero_cnt() {
    int i = blockIdx.x * blockDim.x + threadIdx.x;
    if (i < NN) g_cnt[i] = 0;
}

__global__ void k_hist(const int* __restrict__ col) {
    int e = blockIdx.x * blockDim.x + threadIdx.x;
    if (e < EE) atomicAdd(&g_cnt[col[e]], 1);
}

// single-block exclusive scan over N=100000 counts; also writes dinv, cursor
__global__ void k_scan() {
    __shared__ int sums[1024];
    int t = threadIdx.x;
    const int CH = (NN + 1023) / 1024;   // 98
    int beg = t * CH;
    int end = beg + CH; if (end > NN) end = NN;
    int s = 0;
    for (int i = beg; i < end; i++) s += g_cnt[i];
    sums[t] = s;
    __syncthreads();
    for (int off = 1; off < 1024; off <<= 1) {
        int v = (t >= off) ? sums[t - off] : 0;
        __syncthreads();
        sums[t] += v;
        __syncthreads();
    }
    int run = (t > 0) ? sums[t - 1] : 0;
    for (int i = beg; i < end; i++) {
        g_rowptr[i] = run;
        g_cursor[i] = run;
        g_dinv[i]   = rsqrtf((float)g_cnt[i] + 1.0f);  // +1 self-loop
        run += g_cnt[i];
    }
    if (t == 1023) g_rowptr[NN] = run;   // == EE
}

__global__ void k_scatter(const int* __restrict__ ei) {
    int e = blockIdx.x * blockDim.x + threadIdx.x;
    if (e < EE) {
        int s = ei[e];          // row (source)
        int d = ei[EE + e];     // col (target)
        int p = atomicAdd(&g_cursor[d], 1);
        Edge ed; ed.s = s; ed.w = g_dinv[s] * g_dinv[d];
        g_edge[p] = ed;
    }
}

// ---------------- gather: half-warp per node, float4 lanes, unroll 4 ------
__device__ __forceinline__ float4 gather_row(const float4* __restrict__ x4,
                                             int n, int sub) {
    float4 acc = make_float4(0.f, 0.f, 0.f, 0.f);
    int e = g_rowptr[n], end = g_rowptr[n + 1];
    for (; e + 4 <= end; e += 4) {
        Edge e0 = g_edge[e], e1 = g_edge[e + 1], e2 = g_edge[e + 2], e3 = g_edge[e + 3];
        float4 v0 = __ldg(&x4[(size_t)e0.s * F4 + sub]);
        float4 v1 = __ldg(&x4[(size_t)e1.s * F4 + sub]);
        float4 v2 = __ldg(&x4[(size_t)e2.s * F4 + sub]);
        float4 v3 = __ldg(&x4[(size_t)e3.s * F4 + sub]);
        acc.x = fmaf(e0.w, v0.x, acc.x); acc.y = fmaf(e0.w, v0.y, acc.y);
        acc.z = fmaf(e0.w, v0.z, acc.z); acc.w = fmaf(e0.w, v0.w, acc.w);
        acc.x = fmaf(e1.w, v1.x, acc.x); acc.y = fmaf(e1.w, v1.y, acc.y);
        acc.z = fmaf(e1.w, v1.z, acc.z); acc.w = fmaf(e1.w, v1.w, acc.w);
        acc.x = fmaf(e2.w, v2.x, acc.x); acc.y = fmaf(e2.w, v2.y, acc.y);
        acc.z = fmaf(e2.w, v2.z, acc.z); acc.w = fmaf(e2.w, v2.w, acc.w);
        acc.x = fmaf(e3.w, v3.x, acc.x); acc.y = fmaf(e3.w, v3.y, acc.y);
        acc.z = fmaf(e3.w, v3.z, acc.z); acc.w = fmaf(e3.w, v3.w, acc.w);
    }
    for (; e < end; e++) {
        Edge ed = g_edge[e];
        float4 v = __ldg(&x4[(size_t)ed.s * F4 + sub]);
        acc.x = fmaf(ed.w, v.x, acc.x); acc.y = fmaf(ed.w, v.y, acc.y);
        acc.z = fmaf(ed.w, v.z, acc.z); acc.w = fmaf(ed.w, v.w, acc.w);
    }
    return acc;
}

// ---------------- fused GCN2Conv layer: prop + residual + GEMM + relu ----
__global__ void __launch_bounds__(256)
k_layer(const float* __restrict__ x_in, float* __restrict__ x_out,
        const float* __restrict__ W) {
    __shared__ float4 Wsh[F * F4];   // [k][sub]
    __shared__ float  hs[16][HPAD];
    int t = threadIdx.x;
    const float4* W4 = (const float4*)W;
#pragma unroll
    for (int i = 0; i < 4; i++) Wsh[t + i * 256] = W4[t + i * 256];
    __syncthreads();

    int warp = t >> 5, lane = t & 31, half = lane >> 4, sub = lane & 15;
    int nb = warp * 2 + half;
    int n  = blockIdx.x * 16 + nb;           // grid*16 == NN exactly

    const float4* x4 = (const float4*)x_in;
    float4 acc = gather_row(x4, n, sub);

    float dn = g_dinv[n];
    float sn = dn * dn;                       // self-loop weight
    float4 xn = __ldg(&x4[(size_t)n * F4 + sub]);
    float4 h;
    h.x = (1.f - ALPHA) * (acc.x + sn * xn.x) + ALPHA * xn.x;
    h.y = (1.f - ALPHA) * (acc.y + sn * xn.y) + ALPHA * xn.y;
    h.z = (1.f - ALPHA) * (acc.z + sn * xn.z) + ALPHA * xn.z;
    h.w = (1.f - ALPHA) * (acc.w + sn * xn.w) + ALPHA * xn.w;
    ((float4*)&hs[nb][0])[sub] = h;
    __syncwarp(0xffffffffu);

    float4 o = make_float4(0.f, 0.f, 0.f, 0.f);
#pragma unroll
    for (int k = 0; k < F; k++) {
        float hv = hs[nb][k];
        float4 wk = Wsh[k * F4 + sub];
        o.x = fmaf(hv, wk.x, o.x); o.y = fmaf(hv, wk.y, o.y);
        o.z = fmaf(hv, wk.z, o.z); o.w = fmaf(hv, wk.w, o.w);
    }
    o.x = fmaxf(o.x, 0.f); o.y = fmaxf(o.y, 0.f);
    o.z = fmaxf(o.z, 0.f); o.w = fmaxf(o.w, 0.f);
    ((float4*)x_out)[(size_t)n * F4 + sub] = o;
}

// -------- last GCN2Conv layer fused with GCNConv GEMM: y = relu(...)@Wg ---
__global__ void __launch_bounds__(256)
k_layer_gcn(const float* __restrict__ x_in, float* __restrict__ y_out,
            const float* __restrict__ W, const float* __restrict__ Wg) {
    __shared__ float4 Wsh[F * F4];
    __shared__ float4 Wgs[F * F4];
    __shared__ float  hs[16][HPAD];
    __shared__ float  os[16][HPAD];
    int t = threadIdx.x;
    const float4* W4  = (const float4*)W;
    const float4* Wg4 = (const float4*)Wg;
#pragma unroll
    for (int i = 0; i < 4; i++) {
        Wsh[t + i * 256] = W4[t + i * 256];
        Wgs[t + i * 256] = Wg4[t + i * 256];
    }
    __syncthreads();

    int warp = t >> 5, lane = t & 31, half = lane >> 4, sub = lane & 15;
    int nb = warp * 2 + half;
    int n  = blockIdx.x * 16 + nb;

    const float4* x4 = (const float4*)x_in;
    float4 acc = gather_row(x4, n, sub);

    float dn = g_dinv[n];
    float sn = dn * dn;
    float4 xn = __ldg(&x4[(size_t)n * F4 + sub]);
    float4 h;
    h.x = (1.f - ALPHA) * (acc.x + sn * xn.x) + ALPHA * xn.x;
    h.y = (1.f - ALPHA) * (acc.y + sn * xn.y) + ALPHA * xn.y;
    h.z = (1.f - ALPHA) * (acc.z + sn * xn.z) + ALPHA * xn.z;
    h.w = (1.f - ALPHA) * (acc.w + sn * xn.w) + ALPHA * xn.w;
    ((float4*)&hs[nb][0])[sub] = h;
    __syncwarp(0xffffffffu);

    float4 o = make_float4(0.f, 0.f, 0.f, 0.f);
#pragma unroll
    for (int k = 0; k < F; k++) {
        float hv = hs[nb][k];
        float4 wk = Wsh[k * F4 + sub];
        o.x = fmaf(hv, wk.x, o.x); o.y = fmaf(hv, wk.y, o.y);
        o.z = fmaf(hv, wk.z, o.z); o.w = fmaf(hv, wk.w, o.w);
    }
    o.x = fmaxf(o.x, 0.f); o.y = fmaxf(o.y, 0.f);
    o.z = fmaxf(o.z, 0.f); o.w = fmaxf(o.w, 0.f);

    // second GEMM: y = relu_row @ Wg (separate buffer, no overwrite hazard)
    ((float4*)&os[nb][0])[sub] = o;
    __syncwarp(0xffffffffu);
    float4 y = make_float4(0.f, 0.f, 0.f, 0.f);
#pragma unroll
    for (int k = 0; k < F; k++) {
        float hv = os[nb][k];
        float4 wk = Wgs[k * F4 + sub];
        y.x = fmaf(hv, wk.x, y.x); y.y = fmaf(hv, wk.y, y.y);
        y.z = fmaf(hv, wk.z, y.z); y.w = fmaf(hv, wk.w, y.w);
    }
    ((float4*)y_out)[(size_t)n * F4 + sub] = y;
}

// ---------------- final: h = prop(y)+b_gcn ; out1 = h@W1+b1 ; out2 = h@W2+b2
__global__ void __launch_bounds__(256)
k_final(const float* __restrict__ y, float* __restrict__ out,
        const float* __restrict__ W1, const float* __restrict__ b1,
        const float* __restrict__ W2, const float* __restrict__ b2,
        const float* __restrict__ bg) {
    __shared__ float W1s[F * C1];
    __shared__ float W2s[F * C2];
    __shared__ float bgs[F];
    int t = threadIdx.x;
    if (t < F * C1) W1s[t] = W1[t];
    if (t < F * C2) W2s[t] = W2[t];
    if (t < F)      bgs[t] = bg[t];
    __syncthreads();

    int warp = t >> 5, lane = t & 31, half = lane >> 4, sub = lane & 15;
    int nb = warp * 2 + half;
    int n  = blockIdx.x * 16 + nb;

    const float4* y4 = (const float4*)y;
    float4 acc = gather_row(y4, n, sub);

    float dn = g_dinv[n];
    float sn = dn * dn;
    float4 yn = __ldg(&y4[(size_t)n * F4 + sub]);
    float4 h;
    h.x = acc.x + sn * yn.x + bgs[4 * sub + 0];
    h.y = acc.y + sn * yn.y + bgs[4 * sub + 1];
    h.z = acc.z + sn * yn.z + bgs[4 * sub + 2];
    h.w = acc.w + sn * yn.w + bgs[4 * sub + 3];

    // write h (third output block)
    float* out_h = out + (size_t)NN * (C1 + C2);
    ((float4*)out_h)[(size_t)n * F4 + sub] = h;

    // heads: per-lane partials over its 4 features, reduce across 16 lanes
    float p[C1 + C2];
#pragma unroll
    for (int c = 0; c < C1; c++)
        p[c] = h.x * W1s[(4 * sub + 0) * C1 + c] + h.y * W1s[(4 * sub + 1) * C1 + c]
             + h.z * W1s[(4 * sub + 2) * C1 + c] + h.w * W1s[(4 * sub + 3) * C1 + c];
#pragma unroll
    for (int c = 0; c < C2; c++)
        p[C1 + c] = h.x * W2s[(4 * sub + 0) * C2 + c] + h.y * W2s[(4 * sub + 1) * C2 + c]
                  + h.z * W2s[(4 * sub + 2) * C2 + c] + h.w * W2s[(4 * sub + 3) * C2 + c];
#pragma unroll
    for (int off = 8; off; off >>= 1) {
#pragma unroll
        for (int c = 0; c < C1 + C2; c++)
            p[c] += __shfl_down_sync(0xffffffffu, p[c], off, 16);
    }
    if (sub == 0) {
#pragma unroll
        for (int c = 0; c < C1; c++)
            out[(size_t)n * C1 + c] = p[c] + __ldg(&b1[c]);
        float* o2 = out + (size_t)NN * C1;
#pragma unroll
        for (int c = 0; c < C2; c++)
            o2[(size_t)n * C2 + c] = p[C1 + c] + __ldg(&b2[c]);
    }
}

// ---------------- launch ----------------
extern "C" void kernel_launch(void* const* d_in, const int* in_sizes, int n_in,
                              void* d_out, int out_size) {
    const float* x   = (const float*)d_in[0];
    const int*   ei  = (const int*)  d_in[1];
    const float* Ws  = (const float*)d_in[2];
    const float* Wg  = (const float*)d_in[3];
    const float* bg  = (const float*)d_in[4];
    const float* W1  = (const float*)d_in[5];
    const float* b1  = (const float*)d_in[6];
    const float* W2  = (const float*)d_in[7];
    const float* b2  = (const float*)d_in[8];
    float* out = (float*)d_out;

    float *xa, *xb;
    cudaGetSymbolAddress((void**)&xa, g_xa);
    cudaGetSymbolAddress((void**)&xb, g_xb);

    k_zero_cnt<<<(NN + 255) / 256, 256>>>();
    k_hist<<<(EE + 255) / 256, 256>>>(ei + EE);
    k_scan<<<1, 1024>>>();
    k_scatter<<<(EE + 255) / 256, 256>>>(ei);

    int gb = NN / 16;                               // 6250, exact
    k_layer    <<<gb, 256>>>(x,  xa, Ws);           // layer 0
    k_layer    <<<gb, 256>>>(xa, xb, Ws + F * F);   // layer 1
    k_layer_gcn<<<gb, 256>>>(xb, xa, Ws + 2 * F * F, Wg);  // layer 2 + Wg GEMM
    k_final    <<<gb, 256>>>(xa, out, W1, b1, W2, b2, bg);
}